// round 10
// baseline (speedup 1.0000x reference)
#include <cuda_runtime.h>
#include <cstdint>

#define Bn 2048
#define Tn 512
#define Hn 16
#define Ln 8
#define WPB 7                          // warps per CTA, 2 batches per warp
#define BPC (WPB * 2)                  // 14 batches per CTA
#define NBLK ((Bn + BPC - 1) / BPC)    // 147 CTAs -> 1 per SM
#define CHUNK 16
#define NCHUNK (Tn / CHUNK)

typedef unsigned long long ull;
typedef unsigned int u32;

// Ping-pong scratch for inter-layer hidden sequences (64 MB each).
__device__ float g_bufA[(size_t)Bn * Tn * Hn];
__device__ float g_bufB[(size_t)Bn * Tn * Hn];

// ---- packed fp32x2 ops (Blackwell) ----
__device__ __forceinline__ void ffma2(ull& d, ull a, ull b) {
    asm("fma.rn.f32x2 %0, %1, %2, %0;" : "+l"(d) : "l"(a), "l"(b));
}
__device__ __forceinline__ ull fmul2(ull a, ull b) {
    ull r; asm("mul.rn.f32x2 %0, %1, %2;" : "=l"(r) : "l"(a), "l"(b)); return r;
}
__device__ __forceinline__ float2 u2f(ull a) {
    float2 f;
    asm("mov.b64 {%0,%1}, %2;" : "=f"(f.x), "=f"(f.y) : "l"(a));
    return f;
}
__device__ __forceinline__ ull pack2(float x, float y) {
    ull r;
    asm("mov.b64 %0, {%1,%2};" : "=l"(r) : "f"(x), "f"(y));
    return r;
}
// Load 16 contiguous floats as 8 packed f32x2 (4x 128-bit loads).
__device__ __forceinline__ void load8(ull* d, const float* p) {
    const ulonglong2* q = (const ulonglong2*)p;
    ulonglong2 v0 = q[0], v1 = q[1], v2 = q[2], v3 = q[3];
    d[0] = v0.x; d[1] = v0.y; d[2] = v1.x; d[3] = v1.y;
    d[4] = v2.x; d[5] = v2.y; d[6] = v3.x; d[7] = v3.y;
}
__device__ __forceinline__ float tanha(float x) {
    float r; asm("tanh.approx.f32 %0, %1;" : "=f"(r) : "f"(x)); return r;
}
// Predicated GLOBAL store — single @p STG, no BSSY/BSYNC. Global addresses only!
__device__ __forceinline__ void st_pred(float* addr, float v, int pred) {
    asm volatile("{ .reg .pred p; setp.ne.s32 p, %0, 0; @p st.global.f32 [%1], %2; }"
                 :: "r"(pred), "l"(addr), "f"(v));
}
__device__ __forceinline__ void cp16(u32 saddr, const float* g) {
    asm volatile("cp.async.cg.shared.global [%0], [%1], 16;" :: "r"(saddr), "l"(g));
}
__device__ __forceinline__ void cp_commit() { asm volatile("cp.async.commit_group;"); }
__device__ __forceinline__ void cp_wait0()  { asm volatile("cp.async.wait_group 0;"); }

// One LSTM layer. Warp = TWO batch elements, BOTH carried by every lane
// (two independent register streams -> ILP=2 inside the warp).
// Row split per batch: lanes 0-15 rows (j, 32+j) -> (i, g);
//                      lanes 16-31 rows (16+j, 48+j) -> (f, o).
// Weights shared across the two batches. Sigmoid rows pre-scaled by 0.5.
// h published via unconditional STS into 32-wide slots (lo half = scratch,
// hi half = valid h). x staged via cp.async chunks (2 KB per warp per chunk).
template <bool WRITE_ALL>
__global__ void __launch_bounds__(224, 1)
lstm_layer(const float* __restrict__ in, float* __restrict__ out,
           const float* __restrict__ Wih, const float* __restrict__ Whh,
           const float* __restrict__ bih, const float* __restrict__ bhh)
{
    __shared__ __align__(16) float sh[WPB][2][2][32];          // [warp][parity][batch][lane]; h at [16..31]
    __shared__ __align__(16) float xs[WPB][2][2][CHUNK][Hn];   // [warp][buf][batch][step][j]

    const int warp = threadIdx.x >> 5;
    const int lane = threadIdx.x & 31;
    const int b0 = blockIdx.x * BPC + warp * 2;
    if (b0 >= Bn) return;   // warp-uniform (b0 even; b0+1 also out)
    const int b1 = b0 + 1;

    const int j   = lane & 15;
    const bool lo = lane < 16;
    const int r0  = lane;        // i | f rows (both sigmoid)
    const int r1  = lane + 32;   // g | o rows (tanh | sigmoid)

    // ---- weights -> registers; fold 0.5 into sigmoid rows ----
    ull wx0[8], wh0[8], wx1[8], wh1[8];
    load8(wx0, Wih + r0 * Hn);  load8(wh0, Whh + r0 * Hn);
    load8(wx1, Wih + r1 * Hn);  load8(wh1, Whh + r1 * Hn);
    const ull halfpack = pack2(0.5f, 0.5f);
#pragma unroll
    for (int i = 0; i < 8; i++) {          // r0 always sigmoid
        wx0[i] = fmul2(wx0[i], halfpack);
        wh0[i] = fmul2(wh0[i], halfpack);
    }
    if (!lo) {                             // r1 = o (sigmoid) on hi lanes
#pragma unroll
        for (int i = 0; i < 8; i++) {
            wx1[i] = fmul2(wx1[i], halfpack);
            wh1[i] = fmul2(wh1[i], halfpack);
        }
    }
    const ull bias0 = pack2(0.5f * (bih[r0] + bhh[r0]), 0.0f);
    const ull bias1 = pack2((lo ? 1.0f : 0.5f) * (bih[r1] + bhh[r1]), 0.0f);

    const float pB = lo ? 1.0f : 0.5f;     // tanh(g) | sigmoid(o)
    const float qB = lo ? 0.0f : 0.5f;

    sh[warp][0][0][lane] = 0.0f;           // init h=0 (both halves; only hi half read)
    sh[warp][0][1][lane] = 0.0f;
    float cA = 0.0f, cB = 0.0f;

    const float* xptr0 = in + (size_t)b0 * Tn * Hn;
    const float* xptr1 = in + (size_t)b1 * Tn * Hn;
    float*       orow0 = out + (size_t)b0 * Tn * Hn;
    float*       orow1 = out + (size_t)b1 * Tn * Hn;

    // prefetch chunk 0 (2 KB/warp = 4 cp16 per lane: 2 per batch)
    {
        u32 s0 = (u32)__cvta_generic_to_shared(&xs[warp][0][0][0][0]);
        cp16(s0 + lane * 16,               xptr0 + lane * 4);
        cp16(s0 + (lane + 32) * 16,        xptr0 + (lane + 32) * 4);
        cp16(s0 + (lane + 64) * 16,        xptr1 + lane * 4);
        cp16(s0 + (lane + 96) * 16,        xptr1 + (lane + 32) * 4);
        cp_commit();
    }
    __syncwarp();

    for (int ch = 0; ch < NCHUNK; ch++) {
        const int cur = ch & 1;
        cp_wait0();
        __syncwarp();

        // prefetch chunk ch+1 (clamped refetch at tail — harmless)
        {
            const int nch = (ch + 1 < NCHUNK) ? ch + 1 : ch;
            const float* g0 = xptr0 + nch * (CHUNK * Hn);
            const float* g1 = xptr1 + nch * (CHUNK * Hn);
            u32 s0 = (u32)__cvta_generic_to_shared(&xs[warp][cur ^ 1][0][0][0]);
            cp16(s0 + lane * 16,        g0 + lane * 4);
            cp16(s0 + (lane + 32) * 16, g0 + (lane + 32) * 4);
            cp16(s0 + (lane + 64) * 16, g1 + lane * 4);
            cp16(s0 + (lane + 96) * 16, g1 + (lane + 32) * 4);
            cp_commit();
        }

#pragma unroll 4
        for (int s = 0; s < CHUNK; s++) {
            const int t = ch * CHUNK + s;

            // --- load h for both batches (valid h lives at [16..31]) ---
            ull hpA[8], hpB[8];
            load8(hpA, &sh[warp][s & 1][0][16]);
            load8(hpB, &sh[warp][s & 1][1][16]);
            ull xvA[8], xvB[8];
            load8(xvA, &xs[warp][cur][0][s][0]);
            load8(xvB, &xs[warp][cur][1][s][0]);

            // --- two independent projection streams ---
            ull aA0 = bias0, aA1 = bias1, aB0 = bias0, aB1 = bias1;
#pragma unroll
            for (int i = 0; i < 8; i++) {
                ffma2(aA0, wx0[i], xvA[i]); ffma2(aA1, wx1[i], xvA[i]);
                ffma2(aB0, wx0[i], xvB[i]); ffma2(aB1, wx1[i], xvB[i]);
            }
#pragma unroll
            for (int i = 0; i < 8; i++) {
                ffma2(aA0, wh0[i], hpA[i]); ffma2(aA1, wh1[i], hpA[i]);
                ffma2(aB0, wh0[i], hpB[i]); ffma2(aB1, wh1[i], hpB[i]);
            }

            float2 A0 = u2f(aA0), A1 = u2f(aA1), B0 = u2f(aB0), B1 = u2f(aB1);
            const float vA0 = A0.x + A0.y;   // batch A: i | f (pre-halved)
            const float vA1 = A1.x + A1.y;   // batch A: g | o
            const float vB0 = B0.x + B0.y;   // batch B: i | f
            const float vB1 = B1.x + B1.y;   // batch B: g | o

            // --- activations, two independent chains ---
            const float tA_A = fmaf(0.5f, tanha(vA0), 0.5f);   // sig(i)|sig(f)
            const float tA_B = fmaf(0.5f, tanha(vB0), 0.5f);
            const float tB_A = fmaf(pB, tanha(vA1), qB);       // tanh(g)|sig(o)
            const float tB_B = fmaf(pB, tanha(vB1), qB);

            // lo sends sig(i)*tanh(g); hi sends sig(f)
            const float vA = lo ? (tA_A * tB_A) : tA_A;
            const float vB = lo ? (tA_B * tB_B) : tA_B;
            const float xA = __shfl_xor_sync(0xffffffffu, vA, 16);
            const float xB = __shfl_xor_sync(0xffffffffu, vB, 16);

            cA = fmaf(tA_A, cA, xA);          // valid on hi lanes
            cB = fmaf(tA_B, cB, xB);
            const float hA = tB_A * tanha(cA);
            const float hB = tB_B * tanha(cB);

            // unconditional STS: lo half is scratch, hi half holds valid h
            sh[warp][(s + 1) & 1][0][lane] = hA;
            sh[warp][(s + 1) & 1][1][lane] = hB;
            __syncwarp();
            if (WRITE_ALL || t == Tn - 1) {
                st_pred(orow0 + t * Hn + j, hA, !lo);
                st_pred(orow1 + t * Hn + j, hB, !lo);
            }
        }
    }
}

// Readout: position = last @ Wp^T + bp ; orientation = tanh(last @ Wo^T + bo)
__global__ void head_kernel(const float* __restrict__ hbuf,
                            const float* __restrict__ Wp, const float* __restrict__ bp,
                            const float* __restrict__ Wo, const float* __restrict__ bo,
                            float* __restrict__ out)
{
    int b = blockIdx.x * blockDim.x + threadIdx.x;
    if (b >= Bn) return;
    const float* h = hbuf + (size_t)b * Tn * Hn + (size_t)(Tn - 1) * Hn;
    float hv[16];
#pragma unroll
    for (int i = 0; i < 16; i++) hv[i] = h[i];

#pragma unroll
    for (int r = 0; r < 3; r++) {
        float s = bp[r];
#pragma unroll
        for (int k = 0; k < 16; k++) s += hv[k] * Wp[r * 16 + k];
        out[b * 6 + r] = s;
    }
#pragma unroll
    for (int r = 0; r < 3; r++) {
        float s = bo[r];
#pragma unroll
        for (int k = 0; k < 16; k++) s += hv[k] * Wo[r * 16 + k];
        out[b * 6 + 3 + r] = tanha(s);
    }
}

extern "C" void kernel_launch(void* const* d_in, const int* in_sizes, int n_in,
                              void* d_out, int out_size)
{
    const float* x   = (const float*)d_in[0];
    const float* Wih = (const float*)d_in[1];
    const float* Whh = (const float*)d_in[2];
    const float* bih = (const float*)d_in[3];
    const float* bhh = (const float*)d_in[4];
    const float* Wp  = (const float*)d_in[5];
    const float* bp  = (const float*)d_in[6];
    const float* Wo  = (const float*)d_in[7];
    const float* bo  = (const float*)d_in[8];
    float* out = (float*)d_out;

    float *bufA, *bufB;
    cudaGetSymbolAddress((void**)&bufA, g_bufA);
    cudaGetSymbolAddress((void**)&bufB, g_bufB);

    const float* cur = x;
    for (int l = 0; l < Ln; l++) {
        float* o = (l & 1) ? bufB : bufA;
        if (l != Ln - 1)
            lstm_layer<true><<<NBLK, 224>>>(cur, o,
                                            Wih + (size_t)l * 64 * Hn,
                                            Whh + (size_t)l * 64 * Hn,
                                            bih + (size_t)l * 64,
                                            bhh + (size_t)l * 64);
        else
            lstm_layer<false><<<NBLK, 224>>>(cur, o,
                                             Wih + (size_t)l * 64 * Hn,
                                             Whh + (size_t)l * 64 * Hn,
                                             bih + (size_t)l * 64,
                                             bhh + (size_t)l * 64);
        cur = o;
    }
    head_kernel<<<(Bn + 255) / 256, 256>>>(cur, Wp, bp, Wo, bo, out);
}

// round 11
// speedup vs baseline: 1.1336x; 1.1336x over previous
#include <cuda_runtime.h>
#include <cstdint>

#define Bn 2048
#define Tn 512
#define Hn 16
#define Ln 8
#define CWPB 7                          // consumer warps per CTA (2 batches each)
#define BPC (CWPB * 2)                  // 14 batches per CTA
#define NBLK ((Bn + BPC - 1) / BPC)     // 147 CTAs -> 1 per SM
#define THREADS (CWPB * 2 * 32)         // 448: 7 consumer + 7 producer warps
#define CH 4                            // steps per chunk
#define NCH (Tn / CH)                   // 128 chunks

typedef unsigned long long ull;
typedef unsigned int u32;

// Ping-pong scratch for inter-layer hidden sequences (64 MB each).
__device__ float g_bufA[(size_t)Bn * Tn * Hn];
__device__ float g_bufB[(size_t)Bn * Tn * Hn];

// ---- packed fp32x2 ops (Blackwell) ----
__device__ __forceinline__ void ffma2(ull& d, ull a, ull b) {
    asm("fma.rn.f32x2 %0, %1, %2, %0;" : "+l"(d) : "l"(a), "l"(b));
}
__device__ __forceinline__ ull fmul2(ull a, ull b) {
    ull r; asm("mul.rn.f32x2 %0, %1, %2;" : "=l"(r) : "l"(a), "l"(b)); return r;
}
__device__ __forceinline__ float2 u2f(ull a) {
    float2 f;
    asm("mov.b64 {%0,%1}, %2;" : "=f"(f.x), "=f"(f.y) : "l"(a));
    return f;
}
__device__ __forceinline__ ull pack2(float x, float y) {
    ull r;
    asm("mov.b64 %0, {%1,%2};" : "=l"(r) : "f"(x), "f"(y));
    return r;
}
// Load 16 contiguous floats as 8 packed f32x2 (4x 128-bit loads).
__device__ __forceinline__ void load8(ull* d, const float* p) {
    const ulonglong2* q = (const ulonglong2*)p;
    ulonglong2 v0 = q[0], v1 = q[1], v2 = q[2], v3 = q[3];
    d[0] = v0.x; d[1] = v0.y; d[2] = v1.x; d[3] = v1.y;
    d[4] = v2.x; d[5] = v2.y; d[6] = v3.x; d[7] = v3.y;
}
__device__ __forceinline__ float tanha(float x) {
    float r; asm("tanh.approx.f32 %0, %1;" : "=f"(r) : "f"(x)); return r;
}
// Predicated GLOBAL store — single @p STG, no BSSY/BSYNC. Global addresses only.
__device__ __forceinline__ void st_pred(float* addr, float v, int pred) {
    asm volatile("{ .reg .pred p; setp.ne.s32 p, %0, 0; @p st.global.f32 [%1], %2; }"
                 :: "r"(pred), "l"(addr), "f"(v));
}
__device__ __forceinline__ void cp16(u32 saddr, const float* g) {
    asm volatile("cp.async.cg.shared.global [%0], [%1], 16;" :: "r"(saddr), "l"(g));
}
__device__ __forceinline__ void cp_commit() { asm volatile("cp.async.commit_group;"); }
__device__ __forceinline__ void cp_wait1()  { asm volatile("cp.async.wait_group 1;"); }

// Warp-specialized LSTM layer.
//  Warps 0..6   (consumers): recurrence for 2 batches each; lane (half=batch, j=unit)
//                owns gate rows j,16+j,32+j,48+j; h-proj + activations only.
//  Warps 7..13  (producers): x-projection GEMM one chunk ahead; same batch pairing.
// xproj (bias folded, sigmoid rows pre-halved) flows producers->consumers through a
// double-buffered smem ring, one __syncthreads per CH-step chunk.
template <bool WRITE_ALL>
__global__ void __launch_bounds__(THREADS, 1)
lstm_layer(const float* __restrict__ in, float* __restrict__ out,
           const float* __restrict__ Wih, const float* __restrict__ Whh,
           const float* __restrict__ bih, const float* __restrict__ bhh)
{
    __shared__ __align__(16) float4 xsp[2][CWPB][2][CH][Hn];   // xproj ring [buf][w][half][s][j]
    __shared__ __align__(16) float  xraw[2][CWPB][2][CH][Hn];  // staged x   [buf][w][half][s][j]
    __shared__ __align__(16) float  sh[CWPB][2][2][Hn];        // h exchange [w][parity][half][j]

    const int wid  = threadIdx.x >> 5;
    const int lane = threadIdx.x & 31;
    const int half = lane >> 4;
    const int j    = lane & 15;
    const bool producer = wid >= CWPB;
    const int w = producer ? wid - CWPB : wid;

    int bb = blockIdx.x * BPC + w * 2 + half;       // this lane's batch
    const int valid = bb < Bn;
    if (!valid) bb = 0;                             // clamp: reads safe, stores predicated

    if (!producer) {
        // ================= CONSUMER =================
        // Whh rows for unit j; sigmoid rows (q != 2) pre-scaled by 0.5.
        ull wh[4][8];
        const ull halfpack = pack2(0.5f, 0.5f);
#pragma unroll
        for (int q = 0; q < 4; q++) {
            load8(wh[q], Whh + (q * Hn + j) * Hn);
            if (q != 2) {
#pragma unroll
                for (int i = 0; i < 8; i++) wh[q][i] = fmul2(wh[q][i], halfpack);
            }
        }
        sh[w][0][half][j] = 0.0f;
        float c = 0.0f;
        float* orow = out + (size_t)bb * Tn * Hn;

        __syncthreads();   // producers finished xproj chunk 0

        for (int ch = 0; ch < NCH; ch++) {
            const int buf = ch & 1;
#pragma unroll
            for (int s = 0; s < CH; s++) {
                const int t = ch * CH + s;

                ull hp[8];
                load8(hp, &sh[w][s & 1][half][0]);       // t&1 == s&1 (CH even)
                const float4 xp = xsp[buf][w][half][s][j];

                ull a0 = pack2(xp.x, 0.0f), a1 = pack2(xp.y, 0.0f);
                ull a2 = pack2(xp.z, 0.0f), a3 = pack2(xp.w, 0.0f);
#pragma unroll
                for (int i = 0; i < 8; i++) {
                    ffma2(a0, wh[0][i], hp[i]); ffma2(a1, wh[1][i], hp[i]);
                    ffma2(a2, wh[2][i], hp[i]); ffma2(a3, wh[3][i], hp[i]);
                }
                float2 F0 = u2f(a0), F1 = u2f(a1), F2 = u2f(a2), F3 = u2f(a3);
                const float vi = F0.x + F0.y;   // pre-halved
                const float vf = F1.x + F1.y;   // pre-halved
                const float vg = F2.x + F2.y;
                const float vo = F3.x + F3.y;   // pre-halved

                const float si = fmaf(0.5f, tanha(vi), 0.5f);
                const float sf = fmaf(0.5f, tanha(vf), 0.5f);
                const float tg = tanha(vg);
                const float so = fmaf(0.5f, tanha(vo), 0.5f);

                c = fmaf(sf, c, si * tg);
                const float h = so * tanha(c);

                sh[w][(s + 1) & 1][half][j] = h;
                __syncwarp();
                if (WRITE_ALL || t == Tn - 1)
                    st_pred(orow + t * Hn + j, h, valid);
            }
            __syncthreads();
        }
    } else {
        // ================= PRODUCER =================
        // Wih rows for unit j; sigmoid rows and bias pre-scaled by 0.5; bias folded in.
        ull wx[4][8], bias[4];
        const ull halfpack = pack2(0.5f, 0.5f);
#pragma unroll
        for (int q = 0; q < 4; q++) {
            const int row = q * Hn + j;
            load8(wx[q], Wih + row * Hn);
            float bbv = bih[row] + bhh[row];
            if (q != 2) {
                bbv *= 0.5f;
#pragma unroll
                for (int i = 0; i < 8; i++) wx[q][i] = fmul2(wx[q][i], halfpack);
            }
            bias[q] = pack2(bbv, 0.0f);
        }

        // x-copy lane mapping: lane l copies 16B segment (hb = l>>4, seg = l&15)
        int b0c = blockIdx.x * BPC + w * 2;     int b1c = b0c + 1;
        if (b0c >= Bn) b0c = 0;
        if (b1c >= Bn) b1c = 0;
        const float* xrow_my = in + (size_t)((lane < 16) ? b0c : b1c) * Tn * Hn;
        const int seg = j;                       // 16B segment index within the chunk
        const u32 base0 = (u32)__cvta_generic_to_shared(&xraw[0][w][0][0][0]);
        const u32 base1 = (u32)__cvta_generic_to_shared(&xraw[1][w][0][0][0]);
        const u32 dst_off = (u32)half * (CH * Hn * 4) + (u32)seg * 16;

        // prologue: stage x chunks 0 and 1, compute xproj(0) into xsp[0]
        cp16(base0 + dst_off, xrow_my + 0 * (CH * Hn) + seg * 4);
        cp_commit();
        cp16(base1 + dst_off, xrow_my + 1 * (CH * Hn) + seg * 4);
        cp_commit();
        cp_wait1();       // chunk 0 resident
        __syncwarp();
#pragma unroll
        for (int s = 0; s < CH; s++) {
            ull xv[8];
            load8(xv, &xraw[0][w][half][s][0]);
            ull a0 = bias[0], a1 = bias[1], a2 = bias[2], a3 = bias[3];
#pragma unroll
            for (int i = 0; i < 8; i++) {
                ffma2(a0, wx[0][i], xv[i]); ffma2(a1, wx[1][i], xv[i]);
                ffma2(a2, wx[2][i], xv[i]); ffma2(a3, wx[3][i], xv[i]);
            }
            float2 F0 = u2f(a0), F1 = u2f(a1), F2 = u2f(a2), F3 = u2f(a3);
            xsp[0][w][half][s][j] = make_float4(F0.x + F0.y, F1.x + F1.y,
                                                F2.x + F2.y, F3.x + F3.y);
        }
        __syncthreads();

        for (int ch = 0; ch < NCH; ch++) {
            // prefetch x chunk ch+2 into xraw[ch&1] (clamped at tail)
            const int nc = (ch + 2 < NCH) ? ch + 2 : NCH - 1;
            cp16(((ch & 1) ? base1 : base0) + dst_off,
                 xrow_my + nc * (CH * Hn) + seg * 4);
            cp_commit();

            if (ch + 1 < NCH) {
                cp_wait1();   // x chunk ch+1 resident in xraw[(ch+1)&1]
                __syncwarp();
                const int bi = (ch + 1) & 1;
#pragma unroll
                for (int s = 0; s < CH; s++) {
                    ull xv[8];
                    load8(xv, &xraw[bi][w][half][s][0]);
                    ull a0 = bias[0], a1 = bias[1], a2 = bias[2], a3 = bias[3];
#pragma unroll
                    for (int i = 0; i < 8; i++) {
                        ffma2(a0, wx[0][i], xv[i]); ffma2(a1, wx[1][i], xv[i]);
                        ffma2(a2, wx[2][i], xv[i]); ffma2(a3, wx[3][i], xv[i]);
                    }
                    float2 F0 = u2f(a0), F1 = u2f(a1), F2 = u2f(a2), F3 = u2f(a3);
                    xsp[bi][w][half][s][j] = make_float4(F0.x + F0.y, F1.x + F1.y,
                                                         F2.x + F2.y, F3.x + F3.y);
                }
            }
            __syncthreads();
        }
    }
}

// Readout: position = last @ Wp^T + bp ; orientation = tanh(last @ Wo^T + bo)
__global__ void head_kernel(const float* __restrict__ hbuf,
                            const float* __restrict__ Wp, const float* __restrict__ bp,
                            const float* __restrict__ Wo, const float* __restrict__ bo,
                            float* __restrict__ out)
{
    int b = blockIdx.x * blockDim.x + threadIdx.x;
    if (b >= Bn) return;
    const float* h = hbuf + (size_t)b * Tn * Hn + (size_t)(Tn - 1) * Hn;
    float hv[16];
#pragma unroll
    for (int i = 0; i < 16; i++) hv[i] = h[i];

#pragma unroll
    for (int r = 0; r < 3; r++) {
        float s = bp[r];
#pragma unroll
        for (int k = 0; k < 16; k++) s += hv[k] * Wp[r * 16 + k];
        out[b * 6 + r] = s;
    }
#pragma unroll
    for (int r = 0; r < 3; r++) {
        float s = bo[r];
#pragma unroll
        for (int k = 0; k < 16; k++) s += hv[k] * Wo[r * 16 + k];
        out[b * 6 + 3 + r] = tanha(s);
    }
}

extern "C" void kernel_launch(void* const* d_in, const int* in_sizes, int n_in,
                              void* d_out, int out_size)
{
    const float* x   = (const float*)d_in[0];
    const float* Wih = (const float*)d_in[1];
    const float* Whh = (const float*)d_in[2];
    const float* bih = (const float*)d_in[3];
    const float* bhh = (const float*)d_in[4];
    const float* Wp  = (const float*)d_in[5];
    const float* bp  = (const float*)d_in[6];
    const float* Wo  = (const float*)d_in[7];
    const float* bo  = (const float*)d_in[8];
    float* out = (float*)d_out;

    float *bufA, *bufB;
    cudaGetSymbolAddress((void**)&bufA, g_bufA);
    cudaGetSymbolAddress((void**)&bufB, g_bufB);

    const float* cur = x;
    for (int l = 0; l < Ln; l++) {
        float* o = (l & 1) ? bufB : bufA;
        if (l != Ln - 1)
            lstm_layer<true><<<NBLK, THREADS>>>(cur, o,
                                                Wih + (size_t)l * 64 * Hn,
                                                Whh + (size_t)l * 64 * Hn,
                                                bih + (size_t)l * 64,
                                                bhh + (size_t)l * 64);
        else
            lstm_layer<false><<<NBLK, THREADS>>>(cur, o,
                                                 Wih + (size_t)l * 64 * Hn,
                                                 Whh + (size_t)l * 64 * Hn,
                                                 bih + (size_t)l * 64,
                                                 bhh + (size_t)l * 64);
        cur = o;
    }
    head_kernel<<<(Bn + 255) / 256, 256>>>(cur, Wp, bp, Wo, bo, out);
}